// round 14
// baseline (speedup 1.0000x reference)
#include <cuda_runtime.h>
#include <cuda_fp16.h>
#include <math.h>

#define MAX_NODES 100000
#define F_DIM 128
// g_P fp16, interleaved pair layout, 256 halves per node:
//   src half  (halves   0..127): [w01 a01 w23 a23 ... w(62,63) a(62,63)]
//   dst half  (halves 128..255): same, for the dst projection
//   where w = PW + b1/2 (W1-proj) pairs, a = PA (A1-proj) pairs.
__device__ __half2 g_P[(size_t)MAX_NODES * 128];

// ---------------- mma / ldmatrix helpers ----------------
__device__ __forceinline__ unsigned sm_u32(const void* p) {
    unsigned a;
    asm("{ .reg .u64 t; cvta.to.shared.u64 t, %1; cvt.u32.u64 %0, t; }" : "=r"(a) : "l"(p));
    return a;
}
__device__ __forceinline__ void ldmat4(unsigned& r0, unsigned& r1, unsigned& r2, unsigned& r3,
                                       unsigned addr) {
    asm volatile("ldmatrix.sync.aligned.m8n8.x4.shared.b16 {%0,%1,%2,%3}, [%4];"
                 : "=r"(r0), "=r"(r1), "=r"(r2), "=r"(r3) : "r"(addr));
}
__device__ __forceinline__ void ldmat4t(unsigned& r0, unsigned& r1, unsigned& r2, unsigned& r3,
                                        unsigned addr) {
    asm volatile("ldmatrix.sync.aligned.m8n8.x4.trans.shared.b16 {%0,%1,%2,%3}, [%4];"
                 : "=r"(r0), "=r"(r1), "=r"(r2), "=r"(r3) : "r"(addr));
}
__device__ __forceinline__ void stmat4(unsigned addr, unsigned r0, unsigned r1,
                                       unsigned r2, unsigned r3) {
    asm volatile("stmatrix.sync.aligned.m8n8.x4.shared.b16 [%0], {%1,%2,%3,%4};"
                 :: "r"(addr), "r"(r0), "r"(r1), "r"(r2), "r"(r3) : "memory");
}
__device__ __forceinline__ void mma16816(float* c, unsigned a0, unsigned a1, unsigned a2,
                                         unsigned a3, unsigned b0, unsigned b1) {
    asm volatile(
        "mma.sync.aligned.m16n8k16.row.col.f32.f16.f16.f32 "
        "{%0,%1,%2,%3}, {%4,%5,%6,%7}, {%8,%9}, {%0,%1,%2,%3};"
        : "+f"(c[0]), "+f"(c[1]), "+f"(c[2]), "+f"(c[3])
        : "r"(a0), "r"(a1), "r"(a2), "r"(a3), "r"(b0), "r"(b1));
}
__device__ __forceinline__ unsigned h2u(__half2 h) { return *(unsigned*)&h; }
__device__ __forceinline__ __half2 u2h(unsigned u) { return *(__half2*)&u; }

// ---------------------------------------------------------------------------
// Kernel 1 (fp16 HMMA): P = x @ [W1t|A1t|W1b|A1b], interleaved-pair output.
// stmatrix -> OutS -> interleaving global stores (2x STG.32 per thread).
// smem (halves): Ah[128][136] + Bh[128][72] + OutS[128][72] = 71680 B.
// ---------------------------------------------------------------------------
#define APH 136
#define BPH 72
#define OPH 72
__global__ __launch_bounds__(256, 3)
void precompute_hmma16(const float* __restrict__ x,
                       const float* __restrict__ W1,
                       const float* __restrict__ A1,
                       const float* __restrict__ b1,
                       int n_nodes) {
    extern __shared__ __half ps[];
    __half* Ah   = ps;                        // 128*136 = 17408
    __half* Bh   = ps + 17408;                // 128*72  = 9216
    __half* OutS = ps + 17408 + 9216;         // 128*72  = 9216

    const int tid = threadIdx.x;
    const int m0b = blockIdx.x * 128;
    const int warp = tid >> 5;
    const int lane = tid & 31;
    const int lq = lane & 3;
    const int m0 = warp * 16;

    // ---- stage A: x tile -> fp16, [m][k] pitch 136 ----
    #pragma unroll
    for (int t = 0; t < 16; t++) {
        int i4 = tid + t * 256;               // 0..4095
        int m = i4 >> 5, k4 = i4 & 31;
        int gm = m0b + m;
        float4 v = (gm < n_nodes) ? *(const float4*)(x + (size_t)gm * F_DIM + k4 * 4)
                                  : make_float4(0.f, 0.f, 0.f, 0.f);
        uint2 hv;
        hv.x = h2u(__floats2half2_rn(v.x, v.y));
        hv.y = h2u(__floats2half2_rn(v.z, v.w));
        *(uint2*)(Ah + m * APH + k4 * 4) = hv;
    }

    const unsigned a_hi = sm_u32(Ah) + ((m0 + (lane & 15)) * APH + ((lane >> 4) << 3)) * 2;
    const unsigned o_a  = sm_u32(OutS) + ((m0 + (lane & 15)) * OPH + ((lane >> 4) << 3)) * 2;
    const int bk  = (lane >> 3) & 1;
    const int bn8 = (lane >> 4) & 1;
    const int br  = lane & 7;
    const unsigned bh_base = sm_u32(Bh);
    __half* gph = (__half*)g_P;

    for (int q = 0; q < 4; q++) {
        __syncthreads();   // prior OutS reads done / A ready
        const float* srcq = ((q & 1) ? A1 : W1) + (size_t)(q >> 1) * 128 * 64;
        #pragma unroll
        for (int t = 0; t < 8; t++) {
            int i4 = tid + t * 256;           // 0..2047
            int k = i4 >> 4, n4 = i4 & 15;
            float4 v = *(const float4*)(srcq + k * 64 + n4 * 4);
            uint2 hv;
            hv.x = h2u(__floats2half2_rn(v.x, v.y));
            hv.y = h2u(__floats2half2_rn(v.z, v.w));
            *(uint2*)(Bh + k * BPH + n4 * 4) = hv;
        }
        __syncthreads();

        float acc[8][4];
        #pragma unroll
        for (int nb = 0; nb < 8; nb++)
            #pragma unroll
            for (int c = 0; c < 4; c++) acc[nb][c] = 0.f;

        #pragma unroll
        for (int kb = 0; kb < 8; kb++) {
            unsigned a0, a1, a2, a3;
            ldmat4(a0, a1, a2, a3, a_hi + kb * 32);
            #pragma unroll
            for (int nb2 = 0; nb2 < 4; nb2++) {
                const unsigned off =
                    ((kb * 16 + bk * 8 + br) * BPH + nb2 * 16 + bn8 * 8) * 2;
                unsigned b0, b1r, b2r, b3r;
                ldmat4t(b0, b1r, b2r, b3r, bh_base + off);
                mma16816(acc[2 * nb2],     a0, a1, a2, a3, b0, b1r);
                mma16816(acc[2 * nb2 + 1], a0, a1, a2, a3, b2r, b3r);
            }
        }

        // epilogue: fold b1/2 (W quadrants), pack fp16, stmatrix to OutS
        {
            unsigned regs[16];
            #pragma unroll
            for (int nb = 0; nb < 8; nb++) {
                float a0 = acc[nb][0], a1 = acc[nb][1], a2 = acc[nb][2], a3 = acc[nb][3];
                if (!(q & 1)) {
                    const float2 bb = __ldg((const float2*)(b1 + nb * 8 + 2 * lq));
                    a0 += 0.5f * bb.x; a1 += 0.5f * bb.y;
                    a2 += 0.5f * bb.x; a3 += 0.5f * bb.y;
                }
                regs[2 * nb]     = h2u(__floats2half2_rn(a0, a1));
                regs[2 * nb + 1] = h2u(__floats2half2_rn(a2, a3));
            }
            stmat4(o_a,      regs[0],  regs[1],  regs[2],  regs[3]);
            stmat4(o_a + 32, regs[4],  regs[5],  regs[6],  regs[7]);
            stmat4(o_a + 64, regs[8],  regs[9],  regs[10], regs[11]);
            stmat4(o_a + 96, regs[12], regs[13], regs[14], regs[15]);
        }
        __syncthreads();

        // interleaving global store: quadrant q's uint2 (j-pairs 2c, 2c+1)
        // -> halves base + 8c + 2(q&1)  and  base + 8c + 4 + 2(q&1)
        {
            const int base = (q & 2) ? 128 : 0;
            const int aoff = (q & 1) ? 2 : 0;
            #pragma unroll
            for (int t = 0; t < 8; t++) {
                int i = tid + t * 256;            // 0..2047
                int r = i >> 4, c = i & 15;
                int gm = m0b + r;
                if (gm < n_nodes) {
                    const uint2 v = *(const uint2*)(OutS + r * OPH + c * 4);
                    __half* dst = gph + (size_t)gm * 256 + base + 8 * c + aoff;
                    *(unsigned*)dst = v.x;
                    *(unsigned*)(dst + 4) = v.y;
                }
            }
        }
    }
}

// ---------------------------------------------------------------------------
// Kernel 2 (v11): interleaved fp16 gather -> shuffle-free select-free layer1;
// HMMA layers 2/3 with B-frags via ldmatrix.trans. Warp owns 16 edges.
// ---------------------------------------------------------------------------
#define TILE_E 128
#define H1PH 72   // h1s pitch ([m][k]) and Wc pitch ([k][n])
#define H2PH 40   // h2s pitch ([m][k]) and W3c pitch ([k][n])

__global__ __launch_bounds__(256, 4)
void edge_kernel11(const int* __restrict__ ei,
                   const float* __restrict__ W2, const float* __restrict__ b2,
                   const float* __restrict__ A2,
                   const float* __restrict__ W3, const float* __restrict__ b3,
                   const float* __restrict__ A3,
                   const float* __restrict__ Wf, const float* __restrict__ bf,
                   float* __restrict__ out, int E) {
    extern __shared__ __half hs[];
    __half* h1s = hs;                           // 128*72 = 9216
    __half* h2s = hs + 9216;                    // 128*40 = 5120
    __half* Wc  = hs + 9216 + 5120;             // 64*72  = 4608  [k][n] = [W2|A2]
    __half* W3c = hs + 9216 + 5120 + 4608;      // 32*40  = 1280  [k][n] = [W3|A3]

    const int tid = threadIdx.x;
    const int e_base = blockIdx.x * TILE_E;
    const int warp = tid >> 5;
    const int lane = tid & 31;
    const int lq = lane & 3;
    const int lr = lane >> 2;
    const int m0 = warp * 16;

    // ---- weight staging: [k][n] layout ----
    #pragma unroll
    for (int t = 0; t < 8; t++) {
        int i = tid + t * 256;           // 0..2047 = k*32+n
        int k = i >> 5, n = i & 31;
        Wc[k * H1PH + n]      = __float2half(W2[i]);
        Wc[k * H1PH + 32 + n] = __float2half(A2[i]);
    }
    #pragma unroll
    for (int t = 0; t < 2; t++) {
        int i = tid + t * 256;           // 0..511 = k*16+n
        int k = i >> 4, n = i & 15;
        W3c[k * H2PH + n]      = __float2half(W3[i]);
        W3c[k * H2PH + 16 + n] = __float2half(A3[i]);
    }

    // ---- Stage A: interleaved gather, no exchange/selects ----
    {
        const int l15 = lane & 15;
        unsigned off = 0;
        {
            int eg = e_base + warp * 16 + l15;
            int idx = 0;
            if (eg < E) idx = (lane < 16) ? ei[eg] : ei[(size_t)E + eg];
            idx = min(max(idx, 0), MAX_NODES - 1);
            off = (unsigned)idx * 512u;         // byte offset into g_P
        }
        // lane owns j-pair index = lane (j = 2*lane, 2*lane+1):
        // uint2 at byte lane*8 = (w_pair, a_pair)
        const char* gpb = (const char*)(const void*)g_P + lane * 8;
        const __half2 z = __float2half2_rn(0.f);

        #pragma unroll
        for (int p = 0; p < 8; p++) {
            const unsigned oAs = __shfl_sync(0xffffffffu, off, 2 * p);
            const unsigned oAd = __shfl_sync(0xffffffffu, off, 16 + 2 * p);
            const unsigned oBs = __shfl_sync(0xffffffffu, off, 2 * p + 1);
            const unsigned oBd = __shfl_sync(0xffffffffu, off, 17 + 2 * p);

            const uint2 sa = *(const uint2*)(gpb + oAs);
            const uint2 da = *(const uint2*)(gpb + oAd + 256);
            const uint2 sb = *(const uint2*)(gpb + oBs);
            const uint2 db = *(const uint2*)(gpb + oBd + 256);

            const __half2 wA = __hadd2(u2h(sa.x), u2h(da.x));
            const __half2 aA = __hadd2(u2h(sa.y), u2h(da.y));
            const __half2 wB = __hadd2(u2h(sb.x), u2h(db.x));
            const __half2 aB = __hadd2(u2h(sb.y), u2h(db.y));

            // b1 pre-folded into w; h = relu(relu(w) + a)
            const __half2 hA = __hmax2(__hadd2(__hmax2(wA, z), aA), z);
            const __half2 hB = __hmax2(__hadd2(__hmax2(wB, z), aB), z);

            const int eA = warp * 16 + 2 * p;
            *(unsigned*)(h1s + eA * H1PH + 2 * lane)       = h2u(hA);
            *(unsigned*)(h1s + (eA + 1) * H1PH + 2 * lane) = h2u(hB);
        }
    }
    __syncthreads();

    const int bk  = (lane >> 3) & 1;
    const int bn8 = (lane >> 4) & 1;
    const int br  = lane & 7;

    // ---- Stage B: layer2 via mma, B frags via ldmatrix.trans ----
    const unsigned h1_a = sm_u32(h1s) +
        ((m0 + (lane & 15)) * H1PH + ((lane >> 4) << 3)) * 2;
    const unsigned wc_base = sm_u32(Wc);
    float acc[8][4];
    #pragma unroll
    for (int nb = 0; nb < 8; nb++)
        #pragma unroll
        for (int c = 0; c < 4; c++) acc[nb][c] = 0.f;

    #pragma unroll
    for (int kb = 0; kb < 4; kb++) {
        unsigned a0, a1, a2, a3;
        ldmat4(a0, a1, a2, a3, h1_a + kb * 32);
        #pragma unroll
        for (int nb2 = 0; nb2 < 4; nb2++) {
            const unsigned off =
                ((kb * 16 + bk * 8 + br) * H1PH + nb2 * 16 + bn8 * 8) * 2;
            unsigned b0, b1r, b2r, b3r;
            ldmat4t(b0, b1r, b2r, b3r, wc_base + off);
            mma16816(acc[2 * nb2],     a0, a1, a2, a3, b0, b1r);
            mma16816(acc[2 * nb2 + 1], a0, a1, a2, a3, b2r, b3r);
        }
    }

    {
        unsigned regs[8];
        #pragma unroll
        for (int j = 0; j < 4; j++) {
            const float2 bb = __ldg((const float2*)(b2 + 8 * j + 2 * lq));
            float v0 = fmaxf(fmaxf(acc[j][0] + bb.x, 0.f) + acc[j + 4][0], 0.f);
            float v1 = fmaxf(fmaxf(acc[j][1] + bb.y, 0.f) + acc[j + 4][1], 0.f);
            float v2 = fmaxf(fmaxf(acc[j][2] + bb.x, 0.f) + acc[j + 4][2], 0.f);
            float v3 = fmaxf(fmaxf(acc[j][3] + bb.y, 0.f) + acc[j + 4][3], 0.f);
            regs[2 * j]     = h2u(__floats2half2_rn(v0, v1));
            regs[2 * j + 1] = h2u(__floats2half2_rn(v2, v3));
        }
        const unsigned h2_a = sm_u32(h2s) +
            ((m0 + (lane & 15)) * H2PH + ((lane >> 4) << 3)) * 2;
        stmat4(h2_a,      regs[0], regs[1], regs[2], regs[3]);
        stmat4(h2_a + 32, regs[4], regs[5], regs[6], regs[7]);
    }
    __syncwarp();

    // ---- Stage C: layer3 via mma + head ----
    const unsigned h2_ra = sm_u32(h2s) +
        ((m0 + (lane & 15)) * H2PH + ((lane >> 4) << 3)) * 2;
    const unsigned w3_base = sm_u32(W3c);
    float acc3[4][4];
    #pragma unroll
    for (int nb = 0; nb < 4; nb++)
        #pragma unroll
        for (int c = 0; c < 4; c++) acc3[nb][c] = 0.f;

    #pragma unroll
    for (int kb = 0; kb < 2; kb++) {
        unsigned a0, a1, a2, a3;
        ldmat4(a0, a1, a2, a3, h2_ra + kb * 32);
        #pragma unroll
        for (int nb2 = 0; nb2 < 2; nb2++) {
            const unsigned off =
                ((kb * 16 + bk * 8 + br) * H2PH + nb2 * 16 + bn8 * 8) * 2;
            unsigned b0, b1r, b2r, b3r;
            ldmat4t(b0, b1r, b2r, b3r, w3_base + off);
            mma16816(acc3[2 * nb2],     a0, a1, a2, a3, b0, b1r);
            mma16816(acc3[2 * nb2 + 1], a0, a1, a2, a3, b2r, b3r);
        }
    }

    float pr = 0.f, pr8 = 0.f;
    #pragma unroll
    for (int j = 0; j < 2; j++) {
        const float2 bb = __ldg((const float2*)(b3 + 8 * j + 2 * lq));
        const float2 wf = __ldg((const float2*)(Wf + 8 * j + 2 * lq));
        float v0 = fmaxf(fmaxf(acc3[j][0] + bb.x, 0.f) + acc3[j + 2][0], 0.f);
        float v1 = fmaxf(fmaxf(acc3[j][1] + bb.y, 0.f) + acc3[j + 2][1], 0.f);
        float v2 = fmaxf(fmaxf(acc3[j][2] + bb.x, 0.f) + acc3[j + 2][2], 0.f);
        float v3 = fmaxf(fmaxf(acc3[j][3] + bb.y, 0.f) + acc3[j + 2][3], 0.f);
        pr  += v0 * wf.x + v1 * wf.y;
        pr8 += v2 * wf.x + v3 * wf.y;
    }
    pr  += __shfl_xor_sync(0xffffffffu, pr, 1);
    pr  += __shfl_xor_sync(0xffffffffu, pr, 2);
    pr8 += __shfl_xor_sync(0xffffffffu, pr8, 1);
    pr8 += __shfl_xor_sync(0xffffffffu, pr8, 2);

    if (lq == 0) {
        const float bfv = __ldg(bf);
        int eg = e_base + m0 + lr;
        if (eg < E)     out[eg]     = 1.f / (1.f + expf(-(pr + bfv)));
        if (eg + 8 < E) out[eg + 8] = 1.f / (1.f + expf(-(pr8 + bfv)));
    }
}

// ---------------------------------------------------------------------------
extern "C" void kernel_launch(void* const* d_in, const int* in_sizes, int n_in,
                              void* d_out, int out_size) {
    const float* x  = (const float*)d_in[0];
    const int*   ei = (const int*)d_in[1];
    const float* W1 = (const float*)d_in[2];
    const float* b1 = (const float*)d_in[3];
    const float* A1 = (const float*)d_in[4];
    const float* W2 = (const float*)d_in[5];
    const float* b2 = (const float*)d_in[6];
    const float* A2 = (const float*)d_in[7];
    const float* W3 = (const float*)d_in[8];
    const float* b3 = (const float*)d_in[9];
    const float* A3 = (const float*)d_in[10];
    const float* Wf = (const float*)d_in[11];
    const float* bf = (const float*)d_in[12];
    float* out = (float*)d_out;

    const int n_nodes = in_sizes[0] / F_DIM;
    const int E = in_sizes[1] / 2;

    const int pre_smem = (128 * APH + 128 * BPH + 128 * OPH) * 2;   // 71680
    cudaFuncSetAttribute(precompute_hmma16, cudaFuncAttributeMaxDynamicSharedMemorySize, pre_smem);
    precompute_hmma16<<<(n_nodes + 127) / 128, 256, pre_smem>>>(x, W1, A1, b1, n_nodes);

    const int smem_bytes = (9216 + 5120 + 4608 + 1280) * 2;         // 40448
    cudaFuncSetAttribute(edge_kernel11, cudaFuncAttributeMaxDynamicSharedMemorySize, smem_bytes);
    const int nb = (E + TILE_E - 1) / TILE_E;
    edge_kernel11<<<nb, 256, smem_bytes>>>(ei, W2, b2, A2, W3, b3, A3, Wf, bf, out, E);
}

// round 15
// speedup vs baseline: 1.1286x; 1.1286x over previous
#include <cuda_runtime.h>
#include <cuda_fp16.h>
#include <math.h>

#define MAX_NODES 100000
#define F_DIM 128
// g_P fp16, interleaved pair layout, 256 halves per node:
//   src half (halves   0..127): [w01 a01 w23 a23 ...]
//   dst half (halves 128..255): same for dst projection
//   w = PW + b1/2 (W1-proj) pairs, a = PA (A1-proj) pairs.
__device__ __half2 g_P[(size_t)MAX_NODES * 128];

// ---------------- mma / ldmatrix helpers ----------------
__device__ __forceinline__ unsigned sm_u32(const void* p) {
    unsigned a;
    asm("{ .reg .u64 t; cvta.to.shared.u64 t, %1; cvt.u32.u64 %0, t; }" : "=r"(a) : "l"(p));
    return a;
}
__device__ __forceinline__ void ldmat4(unsigned& r0, unsigned& r1, unsigned& r2, unsigned& r3,
                                       unsigned addr) {
    asm volatile("ldmatrix.sync.aligned.m8n8.x4.shared.b16 {%0,%1,%2,%3}, [%4];"
                 : "=r"(r0), "=r"(r1), "=r"(r2), "=r"(r3) : "r"(addr));
}
__device__ __forceinline__ void ldmat4t(unsigned& r0, unsigned& r1, unsigned& r2, unsigned& r3,
                                        unsigned addr) {
    asm volatile("ldmatrix.sync.aligned.m8n8.x4.trans.shared.b16 {%0,%1,%2,%3}, [%4];"
                 : "=r"(r0), "=r"(r1), "=r"(r2), "=r"(r3) : "r"(addr));
}
__device__ __forceinline__ void stmat4(unsigned addr, unsigned r0, unsigned r1,
                                       unsigned r2, unsigned r3) {
    asm volatile("stmatrix.sync.aligned.m8n8.x4.shared.b16 [%0], {%1,%2,%3,%4};"
                 :: "r"(addr), "r"(r0), "r"(r1), "r"(r2), "r"(r3) : "memory");
}
__device__ __forceinline__ void mma16816(float* c, unsigned a0, unsigned a1, unsigned a2,
                                         unsigned a3, unsigned b0, unsigned b1) {
    asm volatile(
        "mma.sync.aligned.m16n8k16.row.col.f32.f16.f16.f32 "
        "{%0,%1,%2,%3}, {%4,%5,%6,%7}, {%8,%9}, {%0,%1,%2,%3};"
        : "+f"(c[0]), "+f"(c[1]), "+f"(c[2]), "+f"(c[3])
        : "r"(a0), "r"(a1), "r"(a2), "r"(a3), "r"(b0), "r"(b1));
}
__device__ __forceinline__ unsigned h2u(__half2 h) { return *(unsigned*)&h; }
__device__ __forceinline__ __half2 u2h(unsigned u) { return *(__half2*)&u; }

// ---------------------------------------------------------------------------
// Kernel 1 (fp16 HMMA): P = x @ [W1t|A1t|W1b|A1b], interleaved-pair output,
// interleaving done in REGISTERS during a coalesced STG.128 store pass.
// smem (halves): Ah[128][136] + Bh[128][72] + OutW[128][72] + OutA[128][72]
//              = 45056 halves = 90112 B -> 2 blocks/SM.
// ---------------------------------------------------------------------------
#define APH 136
#define BPH 72
#define OPH 72
__global__ __launch_bounds__(256, 2)
void precompute_hmma16(const float* __restrict__ x,
                       const float* __restrict__ W1,
                       const float* __restrict__ A1,
                       const float* __restrict__ b1,
                       int n_nodes) {
    extern __shared__ __half ps[];
    __half* Ah   = ps;                          // 128*136 = 17408
    __half* Bh   = ps + 17408;                  // 128*72  = 9216
    __half* OutW = ps + 17408 + 9216;           // 128*72  = 9216
    __half* OutA = OutW + 9216;                 // 128*72  = 9216

    const int tid = threadIdx.x;
    const int m0b = blockIdx.x * 128;
    const int warp = tid >> 5;
    const int lane = tid & 31;
    const int lq = lane & 3;
    const int m0 = warp * 16;

    // ---- stage A: x tile -> fp16, [m][k] pitch 136 ----
    #pragma unroll
    for (int t = 0; t < 16; t++) {
        int i4 = tid + t * 256;               // 0..4095
        int m = i4 >> 5, k4 = i4 & 31;
        int gm = m0b + m;
        float4 v = (gm < n_nodes) ? *(const float4*)(x + (size_t)gm * F_DIM + k4 * 4)
                                  : make_float4(0.f, 0.f, 0.f, 0.f);
        uint2 hv;
        hv.x = h2u(__floats2half2_rn(v.x, v.y));
        hv.y = h2u(__floats2half2_rn(v.z, v.w));
        *(uint2*)(Ah + m * APH + k4 * 4) = hv;
    }

    const unsigned a_hi = sm_u32(Ah) + ((m0 + (lane & 15)) * APH + ((lane >> 4) << 3)) * 2;
    const unsigned o_w  = sm_u32(OutW) + ((m0 + (lane & 15)) * OPH + ((lane >> 4) << 3)) * 2;
    const unsigned o_a  = sm_u32(OutA) + ((m0 + (lane & 15)) * OPH + ((lane >> 4) << 3)) * 2;
    const int bk  = (lane >> 3) & 1;
    const int bn8 = (lane >> 4) & 1;
    const int br  = lane & 7;
    const unsigned bh_base = sm_u32(Bh);
    __half* gph = (__half*)g_P;

    // h = 0: src half (W1/A1 top rows); h = 1: dst half (bottom rows)
    for (int h = 0; h < 2; h++) {
        #pragma unroll
        for (int wa = 0; wa < 2; wa++) {      // 0: W quadrant, 1: A quadrant
            __syncthreads();   // prior Bh / OutW / OutA reads done; Ah ready
            const float* srcq = (wa ? A1 : W1) + (size_t)h * 128 * 64;
            #pragma unroll
            for (int t = 0; t < 8; t++) {
                int i4 = tid + t * 256;       // 0..2047
                int k = i4 >> 4, n4 = i4 & 15;
                float4 v = *(const float4*)(srcq + k * 64 + n4 * 4);
                uint2 hv;
                hv.x = h2u(__floats2half2_rn(v.x, v.y));
                hv.y = h2u(__floats2half2_rn(v.z, v.w));
                *(uint2*)(Bh + k * BPH + n4 * 4) = hv;
            }
            __syncthreads();

            float acc[8][4];
            #pragma unroll
            for (int nb = 0; nb < 8; nb++)
                #pragma unroll
                for (int c = 0; c < 4; c++) acc[nb][c] = 0.f;

            #pragma unroll
            for (int kb = 0; kb < 8; kb++) {
                unsigned a0, a1, a2, a3;
                ldmat4(a0, a1, a2, a3, a_hi + kb * 32);
                #pragma unroll
                for (int nb2 = 0; nb2 < 4; nb2++) {
                    const unsigned off =
                        ((kb * 16 + bk * 8 + br) * BPH + nb2 * 16 + bn8 * 8) * 2;
                    unsigned b0, b1r, b2r, b3r;
                    ldmat4t(b0, b1r, b2r, b3r, bh_base + off);
                    mma16816(acc[2 * nb2],     a0, a1, a2, a3, b0, b1r);
                    mma16816(acc[2 * nb2 + 1], a0, a1, a2, a3, b2r, b3r);
                }
            }

            // epilogue: b1/2 folded only into W quadrant; stmatrix to OutW/OutA
            unsigned regs[16];
            #pragma unroll
            for (int nb = 0; nb < 8; nb++) {
                float a0 = acc[nb][0], a1 = acc[nb][1], a2 = acc[nb][2], a3 = acc[nb][3];
                if (!wa) {
                    const float2 bb = __ldg((const float2*)(b1 + nb * 8 + 2 * lq));
                    a0 += 0.5f * bb.x; a1 += 0.5f * bb.y;
                    a2 += 0.5f * bb.x; a3 += 0.5f * bb.y;
                }
                regs[2 * nb]     = h2u(__floats2half2_rn(a0, a1));
                regs[2 * nb + 1] = h2u(__floats2half2_rn(a2, a3));
            }
            const unsigned oa = wa ? o_a : o_w;
            stmat4(oa,      regs[0],  regs[1],  regs[2],  regs[3]);
            stmat4(oa + 32, regs[4],  regs[5],  regs[6],  regs[7]);
            stmat4(oa + 64, regs[8],  regs[9],  regs[10], regs[11]);
            stmat4(oa + 96, regs[12], regs[13], regs[14], regs[15]);
        }
        __syncthreads();   // OutW + OutA complete

        // interleave in registers, coalesced STG.128:
        // global uint idx 4c..4c+3 = [W(2c), A(2c), W(2c+1), A(2c+1)]
        #pragma unroll
        for (int t = 0; t < 8; t++) {
            int i = tid + t * 256;            // 0..2047
            int r = i >> 4, c = i & 15;
            int gm = m0b + r;
            if (gm < n_nodes) {
                const uint2 w = *(const uint2*)(OutW + r * OPH + 4 * c);
                const uint2 a = *(const uint2*)(OutA + r * OPH + 4 * c);
                *(uint4*)(gph + (size_t)gm * 256 + h * 128 + 8 * c) =
                    make_uint4(w.x, a.x, w.y, a.y);
            }
        }
    }
}

// ---------------------------------------------------------------------------
// Kernel 2 (v11, unchanged from R14 — 75.5us): interleaved fp16 gather ->
// select/exchange-free layer1; HMMA layers 2/3. Warp owns 16 edges.
// ---------------------------------------------------------------------------
#define TILE_E 128
#define H1PH 72
#define H2PH 40

__global__ __launch_bounds__(256, 4)
void edge_kernel11(const int* __restrict__ ei,
                   const float* __restrict__ W2, const float* __restrict__ b2,
                   const float* __restrict__ A2,
                   const float* __restrict__ W3, const float* __restrict__ b3,
                   const float* __restrict__ A3,
                   const float* __restrict__ Wf, const float* __restrict__ bf,
                   float* __restrict__ out, int E) {
    extern __shared__ __half hs[];
    __half* h1s = hs;                           // 128*72 = 9216
    __half* h2s = hs + 9216;                    // 128*40 = 5120
    __half* Wc  = hs + 9216 + 5120;             // 64*72  = 4608  [k][n] = [W2|A2]
    __half* W3c = hs + 9216 + 5120 + 4608;      // 32*40  = 1280  [k][n] = [W3|A3]

    const int tid = threadIdx.x;
    const int e_base = blockIdx.x * TILE_E;
    const int warp = tid >> 5;
    const int lane = tid & 31;
    const int lq = lane & 3;
    const int lr = lane >> 2;
    const int m0 = warp * 16;

    #pragma unroll
    for (int t = 0; t < 8; t++) {
        int i = tid + t * 256;
        int k = i >> 5, n = i & 31;
        Wc[k * H1PH + n]      = __float2half(W2[i]);
        Wc[k * H1PH + 32 + n] = __float2half(A2[i]);
    }
    #pragma unroll
    for (int t = 0; t < 2; t++) {
        int i = tid + t * 256;
        int k = i >> 4, n = i & 15;
        W3c[k * H2PH + n]      = __float2half(W3[i]);
        W3c[k * H2PH + 16 + n] = __float2half(A3[i]);
    }

    // ---- Stage A: interleaved gather, no exchange/selects ----
    {
        const int l15 = lane & 15;
        unsigned off = 0;
        {
            int eg = e_base + warp * 16 + l15;
            int idx = 0;
            if (eg < E) idx = (lane < 16) ? ei[eg] : ei[(size_t)E + eg];
            idx = min(max(idx, 0), MAX_NODES - 1);
            off = (unsigned)idx * 512u;
        }
        const char* gpb = (const char*)(const void*)g_P + lane * 8;
        const __half2 z = __float2half2_rn(0.f);

        #pragma unroll
        for (int p = 0; p < 8; p++) {
            const unsigned oAs = __shfl_sync(0xffffffffu, off, 2 * p);
            const unsigned oAd = __shfl_sync(0xffffffffu, off, 16 + 2 * p);
            const unsigned oBs = __shfl_sync(0xffffffffu, off, 2 * p + 1);
            const unsigned oBd = __shfl_sync(0xffffffffu, off, 17 + 2 * p);

            const uint2 sa = *(const uint2*)(gpb + oAs);
            const uint2 da = *(const uint2*)(gpb + oAd + 256);
            const uint2 sb = *(const uint2*)(gpb + oBs);
            const uint2 db = *(const uint2*)(gpb + oBd + 256);

            const __half2 wA = __hadd2(u2h(sa.x), u2h(da.x));
            const __half2 aA = __hadd2(u2h(sa.y), u2h(da.y));
            const __half2 wB = __hadd2(u2h(sb.x), u2h(db.x));
            const __half2 aB = __hadd2(u2h(sb.y), u2h(db.y));

            const __half2 hA = __hmax2(__hadd2(__hmax2(wA, z), aA), z);
            const __half2 hB = __hmax2(__hadd2(__hmax2(wB, z), aB), z);

            const int eA = warp * 16 + 2 * p;
            *(unsigned*)(h1s + eA * H1PH + 2 * lane)       = h2u(hA);
            *(unsigned*)(h1s + (eA + 1) * H1PH + 2 * lane) = h2u(hB);
        }
    }
    __syncthreads();

    const int bk  = (lane >> 3) & 1;
    const int bn8 = (lane >> 4) & 1;
    const int br  = lane & 7;

    // ---- Stage B ----
    const unsigned h1_a = sm_u32(h1s) +
        ((m0 + (lane & 15)) * H1PH + ((lane >> 4) << 3)) * 2;
    const unsigned wc_base = sm_u32(Wc);
    float acc[8][4];
    #pragma unroll
    for (int nb = 0; nb < 8; nb++)
        #pragma unroll
        for (int c = 0; c < 4; c++) acc[nb][c] = 0.f;

    #pragma unroll
    for (int kb = 0; kb < 4; kb++) {
        unsigned a0, a1, a2, a3;
        ldmat4(a0, a1, a2, a3, h1_a + kb * 32);
        #pragma unroll
        for (int nb2 = 0; nb2 < 4; nb2++) {
            const unsigned off =
                ((kb * 16 + bk * 8 + br) * H1PH + nb2 * 16 + bn8 * 8) * 2;
            unsigned b0, b1r, b2r, b3r;
            ldmat4t(b0, b1r, b2r, b3r, wc_base + off);
            mma16816(acc[2 * nb2],     a0, a1, a2, a3, b0, b1r);
            mma16816(acc[2 * nb2 + 1], a0, a1, a2, a3, b2r, b3r);
        }
    }

    {
        unsigned regs[8];
        #pragma unroll
        for (int j = 0; j < 4; j++) {
            const float2 bb = __ldg((const float2*)(b2 + 8 * j + 2 * lq));
            float v0 = fmaxf(fmaxf(acc[j][0] + bb.x, 0.f) + acc[j + 4][0], 0.f);
            float v1 = fmaxf(fmaxf(acc[j][1] + bb.y, 0.f) + acc[j + 4][1], 0.f);
            float v2 = fmaxf(fmaxf(acc[j][2] + bb.x, 0.f) + acc[j + 4][2], 0.f);
            float v3 = fmaxf(fmaxf(acc[j][3] + bb.y, 0.f) + acc[j + 4][3], 0.f);
            regs[2 * j]     = h2u(__floats2half2_rn(v0, v1));
            regs[2 * j + 1] = h2u(__floats2half2_rn(v2, v3));
        }
        const unsigned h2_a = sm_u32(h2s) +
            ((m0 + (lane & 15)) * H2PH + ((lane >> 4) << 3)) * 2;
        stmat4(h2_a,      regs[0], regs[1], regs[2], regs[3]);
        stmat4(h2_a + 32, regs[4], regs[5], regs[6], regs[7]);
    }
    __syncwarp();

    // ---- Stage C ----
    const unsigned h2_ra = sm_u32(h2s) +
        ((m0 + (lane & 15)) * H2PH + ((lane >> 4) << 3)) * 2;
    const unsigned w3_base = sm_u32(W3c);
    float acc3[4][4];
    #pragma unroll
    for (int nb = 0; nb < 4; nb++)
        #pragma unroll
        for (int c = 0; c < 4; c++) acc3[nb][c] = 0.f;

    #pragma unroll
    for (int kb = 0; kb < 2; kb++) {
        unsigned a0, a1, a2, a3;
        ldmat4(a0, a1, a2, a3, h2_ra + kb * 32);
        #pragma unroll
        for (int nb2 = 0; nb2 < 2; nb2++) {
            const unsigned off =
                ((kb * 16 + bk * 8 + br) * H2PH + nb2 * 16 + bn8 * 8) * 2;
            unsigned b0, b1r, b2r, b3r;
            ldmat4t(b0, b1r, b2r, b3r, w3_base + off);
            mma16816(acc3[2 * nb2],     a0, a1, a2, a3, b0, b1r);
            mma16816(acc3[2 * nb2 + 1], a0, a1, a2, a3, b2r, b3r);
        }
    }

    float pr = 0.f, pr8 = 0.f;
    #pragma unroll
    for (int j = 0; j < 2; j++) {
        const float2 bb = __ldg((const float2*)(b3 + 8 * j + 2 * lq));
        const float2 wf = __ldg((const float2*)(Wf + 8 * j + 2 * lq));
        float v0 = fmaxf(fmaxf(acc3[j][0] + bb.x, 0.f) + acc3[j + 2][0], 0.f);
        float v1 = fmaxf(fmaxf(acc3[j][1] + bb.y, 0.f) + acc3[j + 2][1], 0.f);
        float v2 = fmaxf(fmaxf(acc3[j][2] + bb.x, 0.f) + acc3[j + 2][2], 0.f);
        float v3 = fmaxf(fmaxf(acc3[j][3] + bb.y, 0.f) + acc3[j + 2][3], 0.f);
        pr  += v0 * wf.x + v1 * wf.y;
        pr8 += v2 * wf.x + v3 * wf.y;
    }
    pr  += __shfl_xor_sync(0xffffffffu, pr, 1);
    pr  += __shfl_xor_sync(0xffffffffu, pr, 2);
    pr8 += __shfl_xor_sync(0xffffffffu, pr8, 1);
    pr8 += __shfl_xor_sync(0xffffffffu, pr8, 2);

    if (lq == 0) {
        const float bfv = __ldg(bf);
        int eg = e_base + m0 + lr;
        if (eg < E)     out[eg]     = 1.f / (1.f + expf(-(pr + bfv)));
        if (eg + 8 < E) out[eg + 8] = 1.f / (1.f + expf(-(pr8 + bfv)));
    }
}

// ---------------------------------------------------------------------------
extern "C" void kernel_launch(void* const* d_in, const int* in_sizes, int n_in,
                              void* d_out, int out_size) {
    const float* x  = (const float*)d_in[0];
    const int*   ei = (const int*)d_in[1];
    const float* W1 = (const float*)d_in[2];
    const float* b1 = (const float*)d_in[3];
    const float* A1 = (const float*)d_in[4];
    const float* W2 = (const float*)d_in[5];
    const float* b2 = (const float*)d_in[6];
    const float* A2 = (const float*)d_in[7];
    const float* W3 = (const float*)d_in[8];
    const float* b3 = (const float*)d_in[9];
    const float* A3 = (const float*)d_in[10];
    const float* Wf = (const float*)d_in[11];
    const float* bf = (const float*)d_in[12];
    float* out = (float*)d_out;

    const int n_nodes = in_sizes[0] / F_DIM;
    const int E = in_sizes[1] / 2;

    const int pre_smem = (128 * APH + 128 * BPH + 2 * 128 * OPH) * 2;   // 90112
    cudaFuncSetAttribute(precompute_hmma16, cudaFuncAttributeMaxDynamicSharedMemorySize, pre_smem);
    precompute_hmma16<<<(n_nodes + 127) / 128, 256, pre_smem>>>(x, W1, A1, b1, n_nodes);

    const int smem_bytes = (9216 + 5120 + 4608 + 1280) * 2;             // 40448
    cudaFuncSetAttribute(edge_kernel11, cudaFuncAttributeMaxDynamicSharedMemorySize, smem_bytes);
    const int nb = (E + TILE_E - 1) / TILE_E;
    edge_kernel11<<<nb, 256, smem_bytes>>>(ei, W2, b2, A2, W3, b3, A3, Wf, bf, out, E);
}